// round 1
// baseline (speedup 1.0000x reference)
#include <cuda_runtime.h>
#include <cuda_bf16.h>
#include <cstdint>

// ---------------------------------------------------------------------------
// Problem constants
// ---------------------------------------------------------------------------
#define DIMC   1024
#define TOKENS 16384              // 4 * 4096
#define F2     2048               // 2 * DIM
#define INV_TEMP 8.0f             // 1 / 0.125
#define N_ITER 10

// ---------------------------------------------------------------------------
// Device scratch (allocation-free rule: __device__ globals)
// ---------------------------------------------------------------------------
__device__ float g_Y[(size_t)TOKENS * F2];        // freq_rect, 128 MB
__device__ float g_mag[(size_t)TOKENS * DIMC];    // 64 MB
__device__ float g_scale[(size_t)TOKENS * DIMC];  // 64 MB
__device__ float g_W[(size_t)DIMC * DIMC];        // 4 MB
__device__ float g_u[DIMC];
__device__ float g_v[DIMC];
__device__ float g_r[DIMC];
__device__ float g_c[DIMC];

// ---------------------------------------------------------------------------
// Sinkhorn kernels.  log_P is kept implicit as  A_ij - u_i - v_j  with
// A = sink_w * INV_TEMP.  Per iteration:
//   r_i = lse_j(A_ij - u_i - v_j) = -u_i + lse_j(A_ij - v_j)
//   c_j = lse_i(A_ij - u_i - v_j) = -v_j + lse_i(A_ij - u_i)
//   u_i += 0.5 r_i ; v_j += 0.5 c_j
// ---------------------------------------------------------------------------
__global__ void sk_init_kernel() {
    int t = threadIdx.x;
    g_u[t] = 0.0f;
    g_v[t] = 0.0f;
}

__global__ void sk_rc_kernel(const float* __restrict__ sw) {
    __shared__ float sdata[DIMC];
    __shared__ float sred[256];
    const int t = threadIdx.x;
    const int b = blockIdx.x;

    if (b < DIMC) {
        // row b
        #pragma unroll 4
        for (int j = t; j < DIMC; j += 256)
            sdata[j] = sw[b * DIMC + j] * INV_TEMP - g_v[j];
    } else {
        const int col = b - DIMC;
        #pragma unroll 4
        for (int i = t; i < DIMC; i += 256)
            sdata[i] = sw[i * DIMC + col] * INV_TEMP - g_u[i];
    }
    __syncthreads();

    float m = -3.0e38f;
    #pragma unroll 4
    for (int j = t; j < DIMC; j += 256) m = fmaxf(m, sdata[j]);
    sred[t] = m;
    __syncthreads();
    #pragma unroll
    for (int s = 128; s > 0; s >>= 1) {
        if (t < s) sred[t] = fmaxf(sred[t], sred[t + s]);
        __syncthreads();
    }
    const float mx = sred[0];
    __syncthreads();

    float sum = 0.0f;
    #pragma unroll 4
    for (int j = t; j < DIMC; j += 256) sum += expf(sdata[j] - mx);
    sred[t] = sum;
    __syncthreads();
    #pragma unroll
    for (int s = 128; s > 0; s >>= 1) {
        if (t < s) sred[t] += sred[t + s];
        __syncthreads();
    }

    if (t == 0) {
        const float lse = mx + logf(sred[0]);
        if (b < DIMC) g_r[b] = lse - g_u[b];
        else          g_c[b - DIMC] = lse - g_v[b - DIMC];
    }
}

__global__ void sk_update_kernel() {
    int t = threadIdx.x;
    g_u[t] += 0.5f * g_r[t];
    g_v[t] += 0.5f * g_c[t];
}

__global__ void sk_final_kernel(const float* __restrict__ sw) {
    int idx = blockIdx.x * 256 + threadIdx.x;   // 0 .. 1M-1
    int i = idx >> 10;
    int j = idx & (DIMC - 1);
    g_W[idx] = expf(sw[idx] * INV_TEMP - g_u[i] - g_v[j]);
}

// ---------------------------------------------------------------------------
// mag:  mag[s,d] = sqrt(Y[s,d]^2 + Y[s,d+1024]^2 + 1e-8)
// ---------------------------------------------------------------------------
__global__ void mag_kernel() {
    const int t = blockIdx.x * 256 + threadIdx.x;   // 0 .. 4194303 (float4)
    const int flat = t * 4;                          // < 16.8M
    const int s = flat >> 10;
    const int d = flat & (DIMC - 1);
    const float4 re = *(const float4*)(g_Y + (size_t)s * F2 + d);
    const float4 im = *(const float4*)(g_Y + (size_t)s * F2 + DIMC + d);
    float4 m;
    m.x = sqrtf(re.x * re.x + im.x * im.x + 1e-8f);
    m.y = sqrtf(re.y * re.y + im.y * im.y + 1e-8f);
    m.z = sqrtf(re.z * re.z + im.z * im.z + 1e-8f);
    m.w = sqrtf(re.w * re.w + im.w * im.w + 1e-8f);
    *(float4*)(g_mag + flat) = m;
}

// ---------------------------------------------------------------------------
// fn-mul: Y[s,f] *= scale[s, f & 1023]   (in place)
// ---------------------------------------------------------------------------
__global__ void fnmul_kernel() {
    const int t = blockIdx.x * 256 + threadIdx.x;   // 0 .. 8388607 (float4)
    const int flat = t * 4;                          // < 33.6M
    const int s = flat >> 11;
    const int f = flat & (F2 - 1);
    const int d = f & (DIMC - 1);
    float4 y = *(const float4*)(g_Y + flat);
    const float4 sc = *(const float4*)(g_scale + (size_t)s * DIMC + d);
    y.x *= sc.x; y.y *= sc.y; y.z *= sc.z; y.w *= sc.w;
    *(float4*)(g_Y + flat) = y;
}

// ---------------------------------------------------------------------------
// SGEMM:  C[m,n] = sum_k A[m,k] * B[n,k]     (A: MxK row-major, B: NxK row-major)
// 128x128 block tile, BK=8, 256 threads, 8x8 per-thread micro-tile,
// double-buffered transposed smem tiles, register prefetch of next k-tile.
// MODE 0: plain store.   MODE 1: C = acc / (E[m,n] + 1e-6)  (scale epilogue)
// ---------------------------------------------------------------------------
template <int MODE>
__global__ __launch_bounds__(256, 2)
void sgemm_abt(const float* __restrict__ A, const float* __restrict__ B,
               float* __restrict__ C, const float* __restrict__ E,
               int M, int N, int K)
{
    __shared__ float As[2][8][128];
    __shared__ float Bs[2][8][128];

    const int bm = blockIdx.y * 128;
    const int bn = blockIdx.x * 128;
    const int tid = threadIdx.x;
    const int tx = tid & 15;    // n dir (16)
    const int ty = tid >> 4;    // m dir (16)
    const int lrow = tid >> 1;          // 0..127
    const int lcol = (tid & 1) << 2;    // 0 or 4

    const float* Ap = A + (size_t)(bm + lrow) * K + lcol;
    const float* Bp = B + (size_t)(bn + lrow) * K + lcol;

    // preload first k-tile
    {
        const float4 av = *(const float4*)Ap;
        const float4 bv = *(const float4*)Bp;
        As[0][lcol + 0][lrow] = av.x; As[0][lcol + 1][lrow] = av.y;
        As[0][lcol + 2][lrow] = av.z; As[0][lcol + 3][lrow] = av.w;
        Bs[0][lcol + 0][lrow] = bv.x; Bs[0][lcol + 1][lrow] = bv.y;
        Bs[0][lcol + 2][lrow] = bv.z; Bs[0][lcol + 3][lrow] = bv.w;
    }
    __syncthreads();

    float acc[8][8];
    #pragma unroll
    for (int i = 0; i < 8; i++)
        #pragma unroll
        for (int j = 0; j < 8; j++) acc[i][j] = 0.0f;

    const int nk = K >> 3;
    int buf = 0;
    for (int kt = 0; kt < nk; ++kt) {
        float4 a2, b2;
        const bool pf = (kt + 1 < nk);
        if (pf) {
            a2 = *(const float4*)(Ap + (kt + 1) * 8);
            b2 = *(const float4*)(Bp + (kt + 1) * 8);
        }
        #pragma unroll
        for (int k = 0; k < 8; ++k) {
            float af[8], bf[8];
            #pragma unroll
            for (int i = 0; i < 8; i++) af[i] = As[buf][k][ty * 8 + i];
            #pragma unroll
            for (int j = 0; j < 8; j++) bf[j] = Bs[buf][k][tx * 8 + j];
            #pragma unroll
            for (int i = 0; i < 8; i++)
                #pragma unroll
                for (int j = 0; j < 8; j++)
                    acc[i][j] = fmaf(af[i], bf[j], acc[i][j]);
        }
        if (pf) {
            buf ^= 1;
            As[buf][lcol + 0][lrow] = a2.x; As[buf][lcol + 1][lrow] = a2.y;
            As[buf][lcol + 2][lrow] = a2.z; As[buf][lcol + 3][lrow] = a2.w;
            Bs[buf][lcol + 0][lrow] = b2.x; Bs[buf][lcol + 1][lrow] = b2.y;
            Bs[buf][lcol + 2][lrow] = b2.z; Bs[buf][lcol + 3][lrow] = b2.w;
            __syncthreads();
        }
    }

    // epilogue
    #pragma unroll
    for (int i = 0; i < 8; i++) {
        const size_t row = (size_t)(bm + ty * 8 + i);
        float* Cp = C + row * N + bn + tx * 8;
        float4 o0 = make_float4(acc[i][0], acc[i][1], acc[i][2], acc[i][3]);
        float4 o1 = make_float4(acc[i][4], acc[i][5], acc[i][6], acc[i][7]);
        if (MODE == 1) {
            const float* Ep = E + row * N + bn + tx * 8;
            const float4 m0 = *(const float4*)Ep;
            const float4 m1 = *(const float4*)(Ep + 4);
            o0.x /= (m0.x + 1e-6f); o0.y /= (m0.y + 1e-6f);
            o0.z /= (m0.z + 1e-6f); o0.w /= (m0.w + 1e-6f);
            o1.x /= (m1.x + 1e-6f); o1.y /= (m1.y + 1e-6f);
            o1.z /= (m1.z + 1e-6f); o1.w /= (m1.w + 1e-6f);
        }
        *(float4*)Cp = o0;
        *(float4*)(Cp + 4) = o1;
    }
}

// ---------------------------------------------------------------------------
// Launch
// ---------------------------------------------------------------------------
extern "C" void kernel_launch(void* const* d_in, const int* in_sizes, int n_in,
                              void* d_out, int out_size)
{
    const float* x      = (const float*)d_in[0];   // [4,4096,1024]
    const float* up_w   = (const float*)d_in[1];   // [2048,1024]
    const float* down_w = (const float*)d_in[2];   // [1024,2048]
    const float* sink_w = (const float*)d_in[3];   // [1024,1024]
    float* out = (float*)d_out;

    float *pY, *pMag, *pScale, *pW;
    cudaGetSymbolAddress((void**)&pY,     g_Y);
    cudaGetSymbolAddress((void**)&pMag,   g_mag);
    cudaGetSymbolAddress((void**)&pScale, g_scale);
    cudaGetSymbolAddress((void**)&pW,     g_W);

    // ---- Sinkhorn projection of sink_w (independent of x) ----
    sk_init_kernel<<<1, 1024>>>();
    for (int it = 0; it < N_ITER; ++it) {
        sk_rc_kernel<<<2 * DIMC, 256>>>(sink_w);
        sk_update_kernel<<<1, 1024>>>();
    }
    sk_final_kernel<<<(DIMC * DIMC) / 256, 256>>>(sink_w);

    // ---- GEMM1: Y = x @ up_w^T   [16384 x 2048] ----
    {
        dim3 grid(F2 / 128, TOKENS / 128);
        sgemm_abt<0><<<grid, 256>>>(x, up_w, pY, nullptr, TOKENS, F2, DIMC);
    }

    // ---- mag ----
    mag_kernel<<<(TOKENS * DIMC / 4) / 256, 256>>>();

    // ---- GEMM2 + scale epilogue: scale = (mag @ W^T) / (mag + 1e-6) ----
    {
        dim3 grid(DIMC / 128, TOKENS / 128);
        sgemm_abt<1><<<grid, 256>>>(pMag, pW, pScale, pMag, TOKENS, DIMC, DIMC);
    }

    // ---- Y *= scale (broadcast over both halves) ----
    fnmul_kernel<<<(TOKENS * F2 / 4) / 256, 256>>>();

    // ---- GEMM3: out = Y @ down_w^T   [16384 x 1024] ----
    {
        dim3 grid(DIMC / 128, TOKENS / 128);
        sgemm_abt<0><<<grid, 256>>>(pY, down_w, out, nullptr, TOKENS, DIMC, F2);
    }
}

// round 4
// speedup vs baseline: 2.7544x; 2.7544x over previous
#include <cuda_runtime.h>
#include <cuda_bf16.h>
#include <cstdint>

// ---------------------------------------------------------------------------
// Problem constants
// ---------------------------------------------------------------------------
#define DIMC   1024
#define TOKENS 16384              // 4 * 4096
#define F2     2048               // 2 * DIM
#define INV_TEMP 8.0f             // 1 / 0.125
#define N_ITER 10

// ---------------------------------------------------------------------------
// Device scratch (allocation-free rule: __device__ globals)
// ---------------------------------------------------------------------------
__device__ float g_Y[(size_t)TOKENS * F2];        // freq_rect f32, 128 MB
__device__ float g_mag[(size_t)TOKENS * DIMC];    // 64 MB (f32 for epilogue div)
__device__ float g_scale[(size_t)TOKENS * DIMC];  // 64 MB
__device__ float g_u[DIMC];
__device__ float g_v[DIMC];
__device__ float g_r[DIMC];
__device__ float g_c[DIMC];

// bf16 hi/lo pre-split operands
__device__ __nv_bfloat16 g_xh[(size_t)TOKENS * DIMC];
__device__ __nv_bfloat16 g_xl[(size_t)TOKENS * DIMC];
__device__ __nv_bfloat16 g_uph[(size_t)F2 * DIMC];
__device__ __nv_bfloat16 g_upl[(size_t)F2 * DIMC];
__device__ __nv_bfloat16 g_dnh[(size_t)DIMC * F2];
__device__ __nv_bfloat16 g_dnl[(size_t)DIMC * F2];
__device__ __nv_bfloat16 g_Wh[(size_t)DIMC * DIMC];
__device__ __nv_bfloat16 g_Wl[(size_t)DIMC * DIMC];
__device__ __nv_bfloat16 g_magh[(size_t)TOKENS * DIMC];
__device__ __nv_bfloat16 g_magl[(size_t)TOKENS * DIMC];
__device__ __nv_bfloat16 g_Yh[(size_t)TOKENS * F2];
__device__ __nv_bfloat16 g_Yl[(size_t)TOKENS * F2];

// ---------------------------------------------------------------------------
// Helpers (sm_80+-safe: ldmatrix / mma.sync / cp.async only)
// ---------------------------------------------------------------------------
__device__ __forceinline__ uint32_t smem_u32(const void* p) {
    uint32_t a;
    asm("{ .reg .u64 t; cvta.to.shared.u64 t, %1; cvt.u32.u64 %0, t; }"
        : "=r"(a) : "l"(p));
    return a;
}

#define CP16(dst, src) \
    asm volatile("cp.async.cg.shared.global [%0], [%1], 16;" \
                 :: "r"(dst), "l"(src))
#define CP_COMMIT() asm volatile("cp.async.commit_group;" ::: "memory")
#define CP_WAIT1()  asm volatile("cp.async.wait_group 1;" ::: "memory")
#define CP_WAIT0()  asm volatile("cp.async.wait_group 0;" ::: "memory")

#define LDSM4(r0, r1, r2, r3, addr) \
    asm volatile("ldmatrix.sync.aligned.m8n8.x4.shared.b16 {%0,%1,%2,%3}, [%4];" \
                 : "=r"(r0), "=r"(r1), "=r"(r2), "=r"(r3) : "r"(addr))

#define MMA_BF16(d, a, B0, B1) \
    asm volatile( \
        "mma.sync.aligned.m16n8k16.row.col.f32.bf16.bf16.f32 " \
        "{%0,%1,%2,%3}, {%4,%5,%6,%7}, {%8,%9}, {%0,%1,%2,%3};" \
        : "+f"((d)[0]), "+f"((d)[1]), "+f"((d)[2]), "+f"((d)[3]) \
        : "r"((a)[0]), "r"((a)[1]), "r"((a)[2]), "r"((a)[3]), \
          "r"(B0), "r"(B1))

__device__ __forceinline__ void split2(float v, __nv_bfloat16& h, __nv_bfloat16& l) {
    h = __float2bfloat16(v);
    l = __float2bfloat16(v - __bfloat162float(h));
}

// ---------------------------------------------------------------------------
// Sinkhorn (coalesced fused row/col logsumexp; implicit log_P = A - u - v)
// ---------------------------------------------------------------------------
__global__ void sk_init_kernel() {
    int t = threadIdx.x;
    g_u[t] = 0.0f;
    g_v[t] = 0.0f;
}

__device__ __forceinline__ void lse_merge(float& m, float& s, float m2, float s2) {
    if (m2 > m) { s = s * expf(m - m2) + s2; m = m2; }
    else        { s += s2 * expf(m2 - m); }
}

__global__ __launch_bounds__(256) void sk_iter_kernel(const float* __restrict__ sw) {
    __shared__ float sh[DIMC];
    __shared__ float smm[16][17];
    __shared__ float sms[16][17];
    const int t = threadIdx.x;
    const int b = blockIdx.x;

    if (b < 64) {
        for (int j = t; j < DIMC; j += 256) sh[j] = g_v[j];
        __syncthreads();
        const int w = t >> 5, lane = t & 31;
        #pragma unroll
        for (int rr = 0; rr < 2; ++rr) {
            const int row = b * 16 + w * 2 + rr;
            float m = -3.0e38f, s = 0.0f;
            for (int j = lane; j < DIMC; j += 32) {
                const float val = sw[row * DIMC + j] * INV_TEMP - sh[j];
                if (val > m) { s = s * expf(m - val) + 1.0f; m = val; }
                else         { s += expf(val - m); }
            }
            #pragma unroll
            for (int off = 16; off; off >>= 1) {
                const float m2 = __shfl_down_sync(0xFFFFFFFFu, m, off);
                const float s2 = __shfl_down_sync(0xFFFFFFFFu, s, off);
                lse_merge(m, s, m2, s2);
            }
            if (lane == 0) g_r[row] = m + logf(s) - g_u[row];
        }
    } else {
        const int c0 = (b - 64) * 16;
        for (int j = t; j < DIMC; j += 256) sh[j] = g_u[j];
        __syncthreads();
        const int tx = t & 15, ty = t >> 4;
        float m = -3.0e38f, s = 0.0f;
        for (int r = ty; r < DIMC; r += 16) {
            const float val = sw[r * DIMC + c0 + tx] * INV_TEMP - sh[r];
            if (val > m) { s = s * expf(m - val) + 1.0f; m = val; }
            else         { s += expf(val - m); }
        }
        smm[ty][tx] = m; sms[ty][tx] = s;
        __syncthreads();
        if (t < 16) {
            float M = smm[0][t], S = sms[0][t];
            #pragma unroll
            for (int k = 1; k < 16; ++k) lse_merge(M, S, smm[k][t], sms[k][t]);
            g_c[c0 + t] = M + logf(S) - g_v[c0 + t];
        }
    }
}

__global__ void sk_update_kernel() {
    int t = threadIdx.x;
    g_u[t] += 0.5f * g_r[t];
    g_v[t] += 0.5f * g_c[t];
}

// W = exp(A - u - v), split straight to bf16 hi/lo
__global__ void sk_final_kernel(const float* __restrict__ sw) {
    int idx = blockIdx.x * 256 + threadIdx.x;
    int i = idx >> 10;
    int j = idx & (DIMC - 1);
    const float w = expf(sw[idx] * INV_TEMP - g_u[i] - g_v[j]);
    split2(w, g_Wh[idx], g_Wl[idx]);
}

// ---------------------------------------------------------------------------
// Generic f32 -> bf16 hi/lo split (4 elems per thread)
// ---------------------------------------------------------------------------
__global__ void split_kernel(const float* __restrict__ src,
                             __nv_bfloat16* __restrict__ h,
                             __nv_bfloat16* __restrict__ l, int n4) {
    const int t = blockIdx.x * 256 + threadIdx.x;
    if (t >= n4) return;
    const float4 v = ((const float4*)src)[t];
    __nv_bfloat16 h0, h1, h2, h3, l0, l1, l2, l3;
    split2(v.x, h0, l0); split2(v.y, h1, l1);
    split2(v.z, h2, l2); split2(v.w, h3, l3);
    ((__nv_bfloat162*)h)[t * 2]     = __nv_bfloat162(h0, h1);
    ((__nv_bfloat162*)h)[t * 2 + 1] = __nv_bfloat162(h2, h3);
    ((__nv_bfloat162*)l)[t * 2]     = __nv_bfloat162(l0, l1);
    ((__nv_bfloat162*)l)[t * 2 + 1] = __nv_bfloat162(l2, l3);
}

// ---------------------------------------------------------------------------
// mag:  mag[s,d] = sqrt(Y[s,d]^2 + Y[s,d+1024]^2 + 1e-8); write f32 + hi/lo
// ---------------------------------------------------------------------------
__global__ void mag_kernel() {
    const int t = blockIdx.x * 256 + threadIdx.x;
    const int flat = t * 4;
    const int s = flat >> 10;
    const int d = flat & (DIMC - 1);
    const float4 re = *(const float4*)(g_Y + (size_t)s * F2 + d);
    const float4 im = *(const float4*)(g_Y + (size_t)s * F2 + DIMC + d);
    float4 m;
    m.x = sqrtf(re.x * re.x + im.x * im.x + 1e-8f);
    m.y = sqrtf(re.y * re.y + im.y * im.y + 1e-8f);
    m.z = sqrtf(re.z * re.z + im.z * im.z + 1e-8f);
    m.w = sqrtf(re.w * re.w + im.w * im.w + 1e-8f);
    *(float4*)(g_mag + flat) = m;
    __nv_bfloat16 h0, h1, h2, h3, l0, l1, l2, l3;
    split2(m.x, h0, l0); split2(m.y, h1, l1);
    split2(m.z, h2, l2); split2(m.w, h3, l3);
    ((__nv_bfloat162*)g_magh)[t * 2]     = __nv_bfloat162(h0, h1);
    ((__nv_bfloat162*)g_magh)[t * 2 + 1] = __nv_bfloat162(h2, h3);
    ((__nv_bfloat162*)g_magl)[t * 2]     = __nv_bfloat162(l0, l1);
    ((__nv_bfloat162*)g_magl)[t * 2 + 1] = __nv_bfloat162(l2, l3);
}

// ---------------------------------------------------------------------------
// fn-mul: Yscaled[s,f] = Y[s,f] * scale[s, f&1023] -> bf16 hi/lo
// ---------------------------------------------------------------------------
__global__ void fnmul_kernel() {
    const int t = blockIdx.x * 256 + threadIdx.x;
    const int flat = t * 4;
    const int s = flat >> 11;
    const int f = flat & (F2 - 1);
    const int d = f & (DIMC - 1);
    float4 y = *(const float4*)(g_Y + flat);
    const float4 sc = *(const float4*)(g_scale + (size_t)s * DIMC + d);
    y.x *= sc.x; y.y *= sc.y; y.z *= sc.z; y.w *= sc.w;
    __nv_bfloat16 h0, h1, h2, h3, l0, l1, l2, l3;
    split2(y.x, h0, l0); split2(y.y, h1, l1);
    split2(y.z, h2, l2); split2(y.w, h3, l3);
    ((__nv_bfloat162*)g_Yh)[t * 2]     = __nv_bfloat162(h0, h1);
    ((__nv_bfloat162*)g_Yh)[t * 2 + 1] = __nv_bfloat162(h2, h3);
    ((__nv_bfloat162*)g_Yl)[t * 2]     = __nv_bfloat162(l0, l1);
    ((__nv_bfloat162*)g_Yl)[t * 2 + 1] = __nv_bfloat162(l2, l3);
}

// ---------------------------------------------------------------------------
// bf16x3 split GEMM via mma.sync:  C[m,n] = sum_k A[m,k]*B[n,k]
//
// CTA 128x128, BK=64, 256 threads = 8 warps (2 x 4), warp tile 64x32.
// Operands pre-split bf16 hi/lo, cp.async double-buffered, SW128-XOR smem.
// 3 products: AhBh + AhBl + AlBh accumulate into one f32 acc.
// MODE 0: C = acc.   MODE 1: C = acc / (E + 1e-6).
// ---------------------------------------------------------------------------
#define BMg 128
#define BNg 128
#define SMBUF 65536
#define OAH 0
#define OAL 16384
#define OBH 32768
#define OBL 49152
#define SM_TOTAL (2 * SMBUF)

template <int MODE>
__global__ __launch_bounds__(256, 1)
void mma_gemm(const __nv_bfloat16* __restrict__ Ah, const __nv_bfloat16* __restrict__ Al,
              const __nv_bfloat16* __restrict__ Bh, const __nv_bfloat16* __restrict__ Bl,
              float* __restrict__ C, const float* __restrict__ E,
              int M, int N, int K)
{
    extern __shared__ char smdyn[];
    const uint32_t smb = smem_u32(smdyn);
    const int tid = threadIdx.x;
    const int lane = tid & 31;
    const int wid  = tid >> 5;
    const int wm = wid >> 2;           // 0..1  (m offset 64*wm)
    const int wn = wid & 3;            // 0..3  (n offset 32*wn)
    const int bm = blockIdx.y * BMg;
    const int bn = blockIdx.x * BNg;
    const int nch = K >> 6;

    // per-chunk async load: 4 tiles x 1024 16B-chunks, 16 per thread
    const int lrow = tid >> 1;               // reused below differently; compute inline
    (void)lrow;

    #define ISSUE_CHUNK(c, buf)                                                 \
    do {                                                                        \
        const int k0_ = (c) * 64;                                               \
        const uint32_t bb_ = smb + (buf) * SMBUF;                               \
        _Pragma("unroll")                                                       \
        for (int i_ = 0; i_ < 4; ++i_) {                                        \
            const int idx_ = i_ * 256 + tid;                                    \
            const int row_ = idx_ >> 3;                                         \
            const int ch_  = idx_ & 7;                                          \
            const uint32_t off_ = (uint32_t)(row_ * 128 + ch_ * 16);            \
            const uint32_t sw_  = off_ ^ ((off_ >> 3) & 0x70);                  \
            const size_t ga_ = (size_t)(bm + row_) * K + k0_ + ch_ * 8;         \
            const size_t gb_ = (size_t)(bn + row_) * K + k0_ + ch_ * 8;         \
            CP16(bb_ + OAH + sw_, Ah + ga_);                                    \
            CP16(bb_ + OAL + sw_, Al + ga_);                                    \
            CP16(bb_ + OBH + sw_, Bh + gb_);                                    \
            CP16(bb_ + OBL + sw_, Bl + gb_);                                    \
        }                                                                       \
        CP_COMMIT();                                                            \
    } while (0)

    ISSUE_CHUNK(0, 0);
    ISSUE_CHUNK(1, 1);

    float acc[4][4][4];
    #pragma unroll
    for (int i = 0; i < 4; ++i)
        #pragma unroll
        for (int j = 0; j < 4; ++j)
            #pragma unroll
            for (int k = 0; k < 4; ++k) acc[i][j][k] = 0.0f;

    // ldmatrix per-thread address components
    const int arow = (lane & 7) + ((lane >> 3) & 1) * 8;  // A: T8-15 -> +8 rows
    const int akd  = ((lane >> 4) & 1) * 8;               // A: T16+  -> +8 k
    const int brow = (lane & 7) + ((lane >> 4) & 1) * 8;  // B: T16+  -> +8 rows
    const int bkd  = ((lane >> 3) & 1) * 8;               // B: T8-15 -> +8 k

    for (int c = 0; c < nch; ++c) {
        if (c < nch - 1) { CP_WAIT1(); } else { CP_WAIT0(); }
        __syncthreads();
        const uint32_t bb = smb + (c & 1) * SMBUF;

        #pragma unroll
        for (int kk = 0; kk < 64; kk += 16) {
            uint32_t ah[2][4], al[2][4], bh[2][4], bl[2][4];
            uint32_t ah2[2][4], al2[2][4];
            // A fragments: mf 0..3 (split into two pairs to limit live range)
            #pragma unroll
            for (int mf = 0; mf < 2; ++mf) {
                const uint32_t off = (uint32_t)((wm * 64 + mf * 16 + arow) * 128 + (kk + akd) * 2);
                const uint32_t sw = off ^ ((off >> 3) & 0x70);
                LDSM4(ah[mf][0], ah[mf][1], ah[mf][2], ah[mf][3], bb + OAH + sw);
                LDSM4(al[mf][0], al[mf][1], al[mf][2], al[mf][3], bb + OAL + sw);
            }
            #pragma unroll
            for (int mf = 0; mf < 2; ++mf) {
                const uint32_t off = (uint32_t)((wm * 64 + (mf + 2) * 16 + arow) * 128 + (kk + akd) * 2);
                const uint32_t sw = off ^ ((off >> 3) & 0x70);
                LDSM4(ah2[mf][0], ah2[mf][1], ah2[mf][2], ah2[mf][3], bb + OAH + sw);
                LDSM4(al2[mf][0], al2[mf][1], al2[mf][2], al2[mf][3], bb + OAL + sw);
            }
            // B fragments: nf pairs (0,1) and (2,3)
            #pragma unroll
            for (int np = 0; np < 2; ++np) {
                const uint32_t off = (uint32_t)((wn * 32 + np * 16 + brow) * 128 + (kk + bkd) * 2);
                const uint32_t sw = off ^ ((off >> 3) & 0x70);
                LDSM4(bh[np][0], bh[np][1], bh[np][2], bh[np][3], bb + OBH + sw);
                LDSM4(bl[np][0], bl[np][1], bl[np][2], bl[np][3], bb + OBL + sw);
            }
            // 48 mma
            #pragma unroll
            for (int mf = 0; mf < 4; ++mf) {
                const uint32_t* Ahf = (mf < 2) ? ah[mf]  : ah2[mf - 2];
                const uint32_t* Alf = (mf < 2) ? al[mf]  : al2[mf - 2];
                #pragma unroll
                for (int nf = 0; nf < 4; ++nf) {
                    const int np = nf >> 1, hh = (nf & 1) * 2;
                    MMA_BF16(acc[mf][nf], Ahf, bh[np][hh], bh[np][hh + 1]);
                    MMA_BF16(acc[mf][nf], Ahf, bl[np][hh], bl[np][hh + 1]);
                    MMA_BF16(acc[mf][nf], Alf, bh[np][hh], bh[np][hh + 1]);
                }
            }
        }
        __syncthreads();
        if (c + 2 < nch) ISSUE_CHUNK(c + 2, c & 1);
    }
    #undef ISSUE_CHUNK

    // epilogue: thread (g=lane/4, tig=lane%4): rows g,g+8; cols 2*tig,+1
    const int g = lane >> 2, tig = lane & 3;
    #pragma unroll
    for (int mf = 0; mf < 4; ++mf) {
        const int r0 = bm + wm * 64 + mf * 16 + g;
        #pragma unroll
        for (int nf = 0; nf < 4; ++nf) {
            const int col = bn + wn * 32 + nf * 8 + tig * 2;
            float2 v0 = make_float2(acc[mf][nf][0], acc[mf][nf][1]);
            float2 v1 = make_float2(acc[mf][nf][2], acc[mf][nf][3]);
            if (MODE == 1) {
                const float2 e0 = *(const float2*)(E + (size_t)r0 * N + col);
                const float2 e1 = *(const float2*)(E + (size_t)(r0 + 8) * N + col);
                v0.x /= (e0.x + 1e-6f); v0.y /= (e0.y + 1e-6f);
                v1.x /= (e1.x + 1e-6f); v1.y /= (e1.y + 1e-6f);
            }
            *(float2*)(C + (size_t)r0 * N + col) = v0;
            *(float2*)(C + (size_t)(r0 + 8) * N + col) = v1;
        }
    }
}

// ---------------------------------------------------------------------------
// Launch
// ---------------------------------------------------------------------------
extern "C" void kernel_launch(void* const* d_in, const int* in_sizes, int n_in,
                              void* d_out, int out_size)
{
    const float* x      = (const float*)d_in[0];   // [4,4096,1024]
    const float* up_w   = (const float*)d_in[1];   // [2048,1024]
    const float* down_w = (const float*)d_in[2];   // [1024,2048]
    const float* sink_w = (const float*)d_in[3];   // [1024,1024]
    float* out = (float*)d_out;

    __nv_bfloat16 *pxh, *pxl, *puph, *pupl, *pdnh, *pdnl, *pWh, *pWl;
    __nv_bfloat16 *pmagh, *pmagl, *pYh, *pYl;
    float *pY, *pMag, *pScale;
    cudaGetSymbolAddress((void**)&pY,     g_Y);
    cudaGetSymbolAddress((void**)&pMag,   g_mag);
    cudaGetSymbolAddress((void**)&pScale, g_scale);
    cudaGetSymbolAddress((void**)&pxh,    g_xh);
    cudaGetSymbolAddress((void**)&pxl,    g_xl);
    cudaGetSymbolAddress((void**)&puph,   g_uph);
    cudaGetSymbolAddress((void**)&pupl,   g_upl);
    cudaGetSymbolAddress((void**)&pdnh,   g_dnh);
    cudaGetSymbolAddress((void**)&pdnl,   g_dnl);
    cudaGetSymbolAddress((void**)&pWh,    g_Wh);
    cudaGetSymbolAddress((void**)&pWl,    g_Wl);
    cudaGetSymbolAddress((void**)&pmagh,  g_magh);
    cudaGetSymbolAddress((void**)&pmagl,  g_magl);
    cudaGetSymbolAddress((void**)&pYh,    g_Yh);
    cudaGetSymbolAddress((void**)&pYl,    g_Yl);

    cudaFuncSetAttribute(mma_gemm<0>, cudaFuncAttributeMaxDynamicSharedMemorySize, SM_TOTAL);
    cudaFuncSetAttribute(mma_gemm<1>, cudaFuncAttributeMaxDynamicSharedMemorySize, SM_TOTAL);

    // ---- pre-split static operands ----
    split_kernel<<<(TOKENS * DIMC / 4 + 255) / 256, 256>>>(x, pxh, pxl, TOKENS * DIMC / 4);
    split_kernel<<<(F2 * DIMC / 4 + 255) / 256, 256>>>(up_w, puph, pupl, F2 * DIMC / 4);
    split_kernel<<<(DIMC * F2 / 4 + 255) / 256, 256>>>(down_w, pdnh, pdnl, DIMC * F2 / 4);

    // ---- Sinkhorn projection (independent of x) ----
    sk_init_kernel<<<1, 1024>>>();
    for (int it = 0; it < N_ITER; ++it) {
        sk_iter_kernel<<<128, 256>>>(sink_w);
        sk_update_kernel<<<1, 1024>>>();
    }
    sk_final_kernel<<<(DIMC * DIMC) / 256, 256>>>(sink_w);

    // ---- GEMM1: Y = x @ up_w^T   [16384 x 2048], K=1024 ----
    {
        dim3 grid(F2 / BNg, TOKENS / BMg);
        mma_gemm<0><<<grid, 256, SM_TOTAL>>>(pxh, pxl, puph, pupl, pY, nullptr,
                                             TOKENS, F2, DIMC);
    }

    // ---- mag (f32 + hi/lo split) ----
    mag_kernel<<<(TOKENS * DIMC / 4) / 256, 256>>>();

    // ---- GEMM2 + epilogue: scale = (mag @ W^T) / (mag + 1e-6), K=1024 ----
    {
        dim3 grid(DIMC / BNg, TOKENS / BMg);
        mma_gemm<1><<<grid, 256, SM_TOTAL>>>(pmagh, pmagl, pWh, pWl, pScale, pMag,
                                             TOKENS, DIMC, DIMC);
    }

    // ---- Yscaled = Y * scale -> bf16 hi/lo ----
    fnmul_kernel<<<(TOKENS * F2 / 4) / 256, 256>>>();

    // ---- GEMM3: out = Yscaled @ down_w^T   [16384 x 1024], K=2048 ----
    {
        dim3 grid(DIMC / BNg, TOKENS / BMg);
        mma_gemm<0><<<grid, 256, SM_TOTAL>>>(pYh, pYl, pdnh, pdnl, out, nullptr,
                                             TOKENS, DIMC, F2);
    }
}